// round 16
// baseline (speedup 1.0000x reference)
#include <cuda_runtime.h>

// Problem constants
#define Bn 16
#define Cn 512
#define Hn 80
#define Wn 80
#define HWn (Hn*Wn)          // 6400
#define CHWn (Cn*HWn)        // 3276800
#define NPIX (Bn*HWn)        // 102400

// counting-sort chunks: 128 pixels per block (proven bookkeeping).
// kfused: 16 channel-groups x 32 pixel-quads = 512 threads, float4 loads.
#define CHUNK_PIX 128
#define NGRP 16
#define GRP_C (Cn/NGRP)                 // 32 channels per group
#define QUADS (CHUNK_PIX/4)             // 32 quads per chunk
#define TPB_F (QUADS*NGRP)              // 512 threads
#define NCHUNK 50                       // chunks per batch (6400/128)
#define NBLK (Bn*NCHUNK)                // 800 blocks
#define NCNT (Bn*Cn*NCHUNK)             // 409600 counters, order (b,c,chunk)

// two-level scan of NCNT counters: 400 blocks x 1024 (R13-proven)
#define K3A_BLKS 400
#define K3A_TPB 1024

// ---- scratch (allocation-free: __device__ globals) ----
__device__ unsigned int g_rec[NPIX * 2];   // 2 det slots/pixel: (c<<16)|rank, ~0u=empty
__device__ unsigned int g_cnt[NCNT];       // counts per (b,c,chunk)
__device__ unsigned int g_off[NCNT];       // exclusive within 1024-superblock
__device__ unsigned int g_bsum[K3A_BLKS];
__device__ unsigned int g_bbase[K3A_BLKS];
__device__ unsigned int g_done;            // last-block ticket (reset by kfused)

// ---------------------------------------------------------------------------
// neighbor test: v (>=0) must be >= all in-bounds raw 3x3 neighbors
// (v >= relu(n) <=> v >= n when v >= 0). Rare path.
__device__ __noinline__ bool neigh_ok(const float* __restrict__ plane,
                                      float v, int h, int w) {
    #pragma unroll
    for (int dh = -1; dh <= 1; dh++) {
        int nh = h + dh;
        if (nh < 0 || nh >= Hn) continue;
        #pragma unroll
        for (int dw = -1; dw <= 1; dw++) {
            if (dh == 0 && dw == 0) continue;
            int nw = w + dw;
            if (nw < 0 || nw >= Wn) continue;
            if (v < plane[nh * Wn + nw]) return false;
        }
    }
    return true;
}

// ---------------------------------------------------------------------------
// Fused: per thread, 4 pixels (float4) x 32 channels.
// Phase A: PURE relu-max stream — one FMNMX per element, nothing else.
// Leader:  global max over groups, then RESCAN only the winning group(s)
//          (L2-resident, ~32 scalar loads) to recover tied channels in
//          ascending order. Exact same predicate as the proven kernels.
// Phase B/C: R13/R14/R15-proven verbatim.
__global__ void __launch_bounds__(TPB_F, 4) kfused(const float* __restrict__ x,
                                                   float4* __restrict__ out4,
                                                   int n4, int half4) {
    __shared__ unsigned int s_mb[NGRP * CHUNK_PIX];    // group max bits
    __shared__ unsigned int bucket[Cn];                // per-channel counts
    __shared__ unsigned int ch[CHUNK_PIX];             // packed det channels

    int blk = blockIdx.x;                    // 800
    int t = threadIdx.x;                     // 512
    int quad = t & (QUADS - 1);              // 0..31
    int grp  = t >> 5;                       // 0..15
    int b     = blk / NCHUNK;
    int chunk = blk - b * NCHUNK;
    int hw0 = chunk * CHUNK_PIX + quad * 4;  // first pixel of this thread's quad
    const float* base = x + (size_t)b * CHWn + (size_t)(grp * GRP_C) * HWn + hw0;

    // folded K0: output padding (proven: leaders cover n4 exactly)
    if (t < CHUNK_PIX) {
        for (int i4 = blk * CHUNK_PIX + t; i4 < n4; i4 += NBLK * CHUNK_PIX) {
            out4[i4] = (i4 < half4) ? make_float4(-1.f, -1.f, -1.f, -1.f)
                                    : make_float4(-4.5f, -4.5f, -4.5f, -4.5f);
        }
    }
    if (blk == 0 && t == 0) g_done = 0u;     // reset last-block ticket each replay

    if (t < Cn) bucket[t] = 0u;              // TPB_F=512=Cn: one each

    // ---- Phase A: pure relu-max over 32 channels x 4 pixels ----
    float m0 = 0.f, m1 = 0.f, m2 = 0.f, m3 = 0.f;   // 0-init absorbs relu
    #pragma unroll 8
    for (int c = 0; c < GRP_C; c++) {
        float4 v = *reinterpret_cast<const float4*>(base + (size_t)c * HWn);
        m0 = fmaxf(m0, v.x);
        m1 = fmaxf(m1, v.y);
        m2 = fmaxf(m2, v.z);
        m3 = fmaxf(m3, v.w);
    }
    {
        int sb = grp * CHUNK_PIX + quad * 4;
        s_mb[sb + 0] = __float_as_uint(m0);
        s_mb[sb + 1] = __float_as_uint(m1);
        s_mb[sb + 2] = __float_as_uint(m2);
        s_mb[sb + 3] = __float_as_uint(m3);
    }
    __syncthreads();

    // ---- leader: global max, rescan winning groups, Phase B, Phase C front ----
    unsigned int c0 = 0xFFFFu, c1 = 0xFFFFu;
    int hw = chunk * CHUNK_PIX + t;          // leader's pixel
    if (t < CHUNK_PIX) {
        unsigned int mb = 0u;
        #pragma unroll
        for (int g = 0; g < NGRP; g++) mb = max(mb, s_mb[g * CHUNK_PIX + t]);

        int h = hw / Wn, w = hw - (hw / Wn) * Wn;
        if (mb != 0u) {                      // relu bits: 0 iff m == 0
            float mv = __uint_as_float(mb);
            unsigned int tA = 0xFFFFu, tB = 0xFFFFu;
            for (int g = 0; g < NGRP; g++) {
                if (s_mb[g * CHUNK_PIX + t] == mb && tB == 0xFFFFu) {
                    // rescan this group's 32 channels (L2-resident, batched loads)
                    const float* gb = x + (size_t)b * CHWn
                                        + (size_t)(g * GRP_C) * HWn + hw;
                    #pragma unroll
                    for (int c = 0; c < GRP_C; c++) {
                        float vv = fmaxf(gb[(size_t)c * HWn], 0.f);
                        if (__float_as_uint(vv) == mb) {
                            unsigned int cc = (unsigned)(g * GRP_C + c);
                            if (tA == 0xFFFFu) tA = cc;
                            else if (tB == 0xFFFFu) tB = cc;
                        }
                    }
                }
            }
            bool d0 = neigh_ok(x + (size_t)b * CHWn + (size_t)tA * HWn, mv, h, w);
            bool d1 = (tB != 0xFFFFu) &&
                      neigh_ok(x + (size_t)b * CHWn + (size_t)tB * HWn, mv, h, w);
            if (d0) { c0 = tA; if (d1) c1 = tB; }
            else if (d1) { c0 = tB; }
        } else {
            // degenerate pixel (all channels <= 0): prob 2^-512; exact rescan.
            int nd = 0;
            for (int c = 0; c < Cn && nd < 2; c++) {
                const float* plane = x + (size_t)b * CHWn + (size_t)c * HWn;
                if (fmaxf(plane[h * Wn + w], 0.f) == 0.f && neigh_ok(plane, 0.f, h, w)) {
                    if (nd == 0) c0 = (unsigned)c; else c1 = (unsigned)c;
                    nd++;
                }
            }
        }
        if (c0 != 0xFFFFu) atomicAdd(&bucket[c0], 1u);
        if (c1 != 0xFFFFu) atomicAdd(&bucket[c1], 1u);
        ch[t] = c0 | (c1 << 16);
    }
    __syncthreads();

    // ---- Phase C back half: exact pixel-order ranks (proven) ----
    if (t < CHUNK_PIX) {
        unsigned int r0 = 0, r1 = 0;
        if (c0 != 0xFFFFu) {
            for (int q = 0; q < t; q++) {
                unsigned int wv = ch[q];
                unsigned int lo = wv & 0xFFFFu, hi = wv >> 16;
                r0 += (lo == c0) + (hi == c0);
                r1 += (lo == c1) + (hi == c1);
            }
        }
        int p = b * HWn + hw;
        g_rec[2*p + 0] = (c0 != 0xFFFFu) ? ((c0 << 16) | r0) : 0xFFFFFFFFu;
        g_rec[2*p + 1] = (c1 != 0xFFFFu) ? ((c1 << 16) | r1) : 0xFFFFFFFFu;
    }
    if (t < Cn)
        g_cnt[(b * Cn + t) * NCHUNK + chunk] = bucket[t];
}

// ---------------------------------------------------------------------------
// K3a: 400 blocks x 1024 counts + last-block k3b base scan (R13-proven).
__global__ void __launch_bounds__(K3A_TPB) k3a_scan() {
    int sb = blockIdx.x;
    int t = threadIdx.x;
    int lane = t & 31;
    int warp = t >> 5;
    unsigned int v = g_cnt[sb * K3A_TPB + t];
    unsigned int incl = v;
    #pragma unroll
    for (int off = 1; off < 32; off <<= 1) {
        unsigned int n = __shfl_up_sync(0xFFFFFFFFu, incl, off);
        if (lane >= off) incl += n;
    }
    __shared__ unsigned int ws[32];
    if (lane == 31) ws[warp] = incl;
    __syncthreads();
    if (t < 32) {
        unsigned int w = ws[t];
        unsigned int iw = w;
        #pragma unroll
        for (int off = 1; off < 32; off <<= 1) {
            unsigned int n = __shfl_up_sync(0xFFFFFFFFu, iw, off);
            if (t >= off) iw += n;
        }
        ws[t] = iw - w;                     // exclusive warp base
        if (t == 31) g_bsum[sb] = iw;       // superblock total
    }
    __syncthreads();
    g_off[sb * K3A_TPB + t] = ws[warp] + (incl - v);

    // ---- last-block merge of the k3b base scan ----
    __threadfence();
    __shared__ unsigned int s_last;
    if (t == 0) {
        unsigned int old = atomicAdd(&g_done, 1u);
        s_last = (old == K3A_BLKS - 1) ? 1u : 0u;
    }
    __syncthreads();
    if (s_last) {
        unsigned int bv = (t < K3A_BLKS) ? g_bsum[t] : 0u;
        unsigned int bincl = bv;
        #pragma unroll
        for (int off = 1; off < 32; off <<= 1) {
            unsigned int n = __shfl_up_sync(0xFFFFFFFFu, bincl, off);
            if (lane >= off) bincl += n;
        }
        __shared__ unsigned int ws2[32];
        if (lane == 31) ws2[warp] = bincl;
        __syncthreads();
        if (t < 32) {
            unsigned int wv = ws2[t];
            unsigned int iw = wv;
            #pragma unroll
            for (int off = 1; off < 32; off <<= 1) {
                unsigned int n = __shfl_up_sync(0xFFFFFFFFu, iw, off);
                if (t >= off) iw += n;
            }
            ws2[t] = iw - wv;
        }
        __syncthreads();
        if (t < K3A_BLKS) g_bbase[t] = ws2[warp] + (bincl - bv);
    }
}

// ---------------------------------------------------------------------------
// K4: place each detection at its globally sorted position (proven).
__global__ void __launch_bounds__(CHUNK_PIX) k4_write(float* __restrict__ out, int nmax) {
    int blk = blockIdx.x;
    int t = threadIdx.x;
    int b     = blk / NCHUNK;
    int chunk = blk - b * NCHUNK;
    int hw = chunk * CHUNK_PIX + t;
    int p  = b * HWn + hw;
    float h = (float)(hw / Wn);
    float w = (float)(hw % Wn);
    float* kp = out + 2u * (unsigned)nmax;
    #pragma unroll
    for (int slot = 0; slot < 2; slot++) {
        unsigned int rec = g_rec[2*p + slot];
        if (rec != 0xFFFFFFFFu) {
            unsigned int c    = rec >> 16;
            unsigned int rank = rec & 0xFFFFu;
            unsigned int idx  = (unsigned)((b * Cn + (int)c) * NCHUNK + chunk);
            unsigned int n = g_bbase[idx >> 10] + g_off[idx] + rank;
            if (n < (unsigned)nmax) {
                out[2u*n + 0u] = h;
                out[2u*n + 1u] = w;
                kp [2u*n + 0u] = 8.0f * h + 3.5f;   // ((p*2+.5)*2+.5)*2+.5
                kp [2u*n + 1u] = 8.0f * w + 3.5f;
            }
        }
    }
}

// ---------------------------------------------------------------------------
extern "C" void kernel_launch(void* const* d_in, const int* in_sizes, int n_in,
                              void* d_out, int out_size) {
    const float* x = (const float*)d_in[0];
    float* out = (float*)d_out;
    int nmax = out_size / 4;
    int n4 = out_size / 4;          // float4 count
    int half4 = (out_size / 2) / 4;

    kfused<<<NBLK, TPB_F>>>(x, (float4*)out, n4, half4);  // pure-max stream + rescan
    k3a_scan<<<K3A_BLKS, K3A_TPB>>>();                    // scan + last-block bases
    k4_write<<<NBLK, CHUNK_PIX>>>(out, nmax);
}

// round 17
// speedup vs baseline: 1.9037x; 1.9037x over previous
#include <cuda_runtime.h>

// Problem constants
#define Bn 16
#define Cn 512
#define Hn 80
#define Wn 80
#define HWn (Hn*Wn)          // 6400
#define CHWn (Cn*HWn)        // 3276800
#define NPIX (Bn*HWn)        // 102400

// counting-sort chunks: 128 pixels per block (proven bookkeeping).
// kfused: 16 channel-groups x 32 pixel-quads = 512 threads, float4 loads.
#define CHUNK_PIX 128
#define NGRP 16
#define GRP_C (Cn/NGRP)                 // 32 channels per group = 1 mask word
#define QUADS (CHUNK_PIX/4)             // 32 quads per chunk
#define TPB_F (QUADS*NGRP)              // 512 threads
#define NCHUNK 50                       // chunks per batch (6400/128)
#define NBLK (Bn*NCHUNK)                // 800 blocks
#define NCNT (Bn*Cn*NCHUNK)             // 409600 counters, order (b,c,chunk)

// two-level scan of NCNT counters: 400 blocks x 1024 (R13-proven)
#define K3A_BLKS 400
#define K3A_TPB 1024

// ---- scratch (allocation-free: __device__ globals) ----
__device__ unsigned int g_rec[NPIX * 2];   // 2 det slots/pixel: (c<<16)|rank, ~0u=empty
__device__ unsigned int g_cnt[NCNT];       // counts per (b,c,chunk)
__device__ unsigned int g_off[NCNT];       // exclusive within 1024-superblock
__device__ unsigned int g_bsum[K3A_BLKS];
__device__ unsigned int g_bbase[K3A_BLKS];
__device__ unsigned int g_done;            // last-block ticket (reset by kfused)

// neighbor offset list (8 in-plane neighbors, fixed order)
__device__ __constant__ signed char NB[8][2] = {
    {-1,-1},{-1,0},{-1,1},{0,-1},{0,1},{1,-1},{1,0},{1,1}
};

// ---------------------------------------------------------------------------
// full 3x3 test (used only on the never-taken degenerate path)
__device__ __noinline__ bool neigh_ok(const float* __restrict__ plane,
                                      float v, int h, int w) {
    #pragma unroll
    for (int dh = -1; dh <= 1; dh++) {
        int nh = h + dh;
        if (nh < 0 || nh >= Hn) continue;
        #pragma unroll
        for (int dw = -1; dw <= 1; dw++) {
            if (dh == 0 && dw == 0) continue;
            int nw = w + dw;
            if (nw < 0 || nw >= Wn) continue;
            if (v < plane[nh * Wn + nw]) return false;
        }
    }
    return true;
}

// ---------------------------------------------------------------------------
// Fused: per thread, 4 pixels (float4) x 32 channels, R15-proven bitmask ties.
// NEW: the 3x3 neighbor checks are distributed over ALL 512 threads
// (4 workers per pixel x 2 neighbors) instead of leader-only.
__global__ void __launch_bounds__(TPB_F, 3) kfused(const float* __restrict__ x,
                                                   float4* __restrict__ out4,
                                                   int n4, int half4) {
    __shared__ unsigned int s_mb[NGRP * CHUNK_PIX];    // group max bits
    __shared__ unsigned int s_mask[NGRP * CHUNK_PIX];  // channels tying group max
    __shared__ unsigned int bucket[Cn];                // per-channel counts
    __shared__ unsigned int ch[CHUNK_PIX];             // packed det channels
    __shared__ unsigned int s_tab[CHUNK_PIX];          // tA | tB<<16 per pixel
    __shared__ unsigned int s_mv[CHUNK_PIX];           // pixel max bits
    __shared__ unsigned int s_ok[CHUNK_PIX];           // bit0: tA ok, bit1: tB ok

    int blk = blockIdx.x;                    // 800
    int t = threadIdx.x;                     // 512
    int quad = t & (QUADS - 1);              // 0..31
    int grp  = t >> 5;                       // 0..15
    int b     = blk / NCHUNK;
    int chunk = blk - b * NCHUNK;
    int hw0 = chunk * CHUNK_PIX + quad * 4;  // first pixel of this thread's quad
    const float* base = x + (size_t)b * CHWn + (size_t)(grp * GRP_C) * HWn + hw0;
    const float* xb = x + (size_t)b * CHWn;  // batch base

    // folded K0: output padding (proven: leaders cover n4 exactly)
    if (t < CHUNK_PIX) {
        for (int i4 = blk * CHUNK_PIX + t; i4 < n4; i4 += NBLK * CHUNK_PIX) {
            out4[i4] = (i4 < half4) ? make_float4(-1.f, -1.f, -1.f, -1.f)
                                    : make_float4(-4.5f, -4.5f, -4.5f, -4.5f);
        }
    }
    if (blk == 0 && t == 0) g_done = 0u;     // reset last-block ticket each replay

    if (t < Cn) bucket[t] = 0u;              // TPB_F=512=Cn: one each

    // ---- Phase A: running max + tie bitmask (R15-proven verbatim) ----
    float m0 = 0.f, m1 = 0.f, m2 = 0.f, m3 = 0.f;
    unsigned int k0 = 0u, k1 = 0u, k2 = 0u, k3 = 0u;
    #pragma unroll 8
    for (int c = 0; c < GRP_C; c++) {
        float4 v = *reinterpret_cast<const float4*>(base + (size_t)c * HWn);
        v.x = fmaxf(v.x, 0.f); v.y = fmaxf(v.y, 0.f);
        v.z = fmaxf(v.z, 0.f); v.w = fmaxf(v.w, 0.f);
        unsigned int bit = 1u << c;
        if (v.x > m0)       { m0 = v.x; k0 = bit; }
        else if (v.x == m0) { k0 |= bit; }
        if (v.y > m1)       { m1 = v.y; k1 = bit; }
        else if (v.y == m1) { k1 |= bit; }
        if (v.z > m2)       { m2 = v.z; k2 = bit; }
        else if (v.z == m2) { k2 |= bit; }
        if (v.w > m3)       { m3 = v.w; k3 = bit; }
        else if (v.w == m3) { k3 |= bit; }
    }
    {
        int sb = grp * CHUNK_PIX + quad * 4;
        s_mb[sb + 0] = __float_as_uint(m0);  s_mask[sb + 0] = k0;
        s_mb[sb + 1] = __float_as_uint(m1);  s_mask[sb + 1] = k1;
        s_mb[sb + 2] = __float_as_uint(m2);  s_mask[sb + 2] = k2;
        s_mb[sb + 3] = __float_as_uint(m3);  s_mask[sb + 3] = k3;
    }
    __syncthreads();

    // ---- leaders: merge groups -> (mv, tA, tB); publish for workers ----
    if (t < CHUNK_PIX) {
        unsigned int mb = 0u;
        #pragma unroll
        for (int g = 0; g < NGRP; g++) mb = max(mb, s_mb[g * CHUNK_PIX + t]);
        unsigned int tA = 0xFFFFu, tB = 0xFFFFu;
        if (mb != 0u) {                         // relu bits: 0 iff m == 0
            #pragma unroll
            for (int g = 0; g < NGRP; g++) {
                int gi = g * CHUNK_PIX + t;
                if (s_mb[gi] == mb) {
                    unsigned int mk = s_mask[gi];
                    while (mk && tB == 0xFFFFu) {   // ascending channel order
                        int bit = __ffs(mk) - 1;
                        mk &= mk - 1;
                        unsigned int cc = (unsigned)(g * GRP_C + bit);
                        if (tA == 0xFFFFu) tA = cc; else tB = cc;
                    }
                }
            }
        }
        s_mv[t]  = mb;
        s_tab[t] = tA | (tB << 16);
        s_ok[t]  = 3u;
    }
    __syncthreads();

    // ---- workers: 4 threads per pixel, 2 neighbors each ----
    {
        int pix  = t & (CHUNK_PIX - 1);
        int part = t >> 7;                    // 0..3
        unsigned int tab = s_tab[pix];
        unsigned int tA = tab & 0xFFFFu, tB = tab >> 16;
        if (tA != 0xFFFFu) {
            float mv = __uint_as_float(s_mv[pix]);
            int hw = chunk * CHUNK_PIX + pix;
            int h = hw / Wn, w = hw - (hw / Wn) * Wn;
            unsigned int fail = 0u;
            #pragma unroll
            for (int k = 0; k < 2; k++) {
                int nh = h + NB[2*part + k][0];
                int nw = w + NB[2*part + k][1];
                if (nh >= 0 && nh < Hn && nw >= 0 && nw < Wn) {
                    int off = nh * Wn + nw;
                    if (mv < xb[(size_t)tA * HWn + off]) fail |= 1u;
                    if (tB != 0xFFFFu && mv < xb[(size_t)tB * HWn + off]) fail |= 2u;
                }
            }
            if (fail) atomicAnd(&s_ok[pix], ~fail);
        }
    }
    __syncthreads();

    // ---- leaders: finalize detections (R15 d0/d1 logic via flags) ----
    unsigned int c0 = 0xFFFFu, c1 = 0xFFFFu;
    int hw = chunk * CHUNK_PIX + t;          // leader's pixel
    if (t < CHUNK_PIX) {
        unsigned int tab = s_tab[t];
        unsigned int tA = tab & 0xFFFFu, tB = tab >> 16;
        if (tA != 0xFFFFu) {
            unsigned int ok = s_ok[t];
            bool d0 = (ok & 1u) != 0u;
            bool d1 = (tB != 0xFFFFu) && ((ok & 2u) != 0u);
            if (d0) { c0 = tA; if (d1) c1 = tB; }
            else if (d1) { c0 = tB; }
        } else if (s_mv[t] == 0u) {
            // degenerate pixel (all channels <= 0): prob 2^-512; exact rescan.
            int h = hw / Wn, w = hw - (hw / Wn) * Wn;
            int nd = 0;
            for (int c = 0; c < Cn && nd < 2; c++) {
                const float* plane = xb + (size_t)c * HWn;
                if (fmaxf(plane[h * Wn + w], 0.f) == 0.f && neigh_ok(plane, 0.f, h, w)) {
                    if (nd == 0) c0 = (unsigned)c; else c1 = (unsigned)c;
                    nd++;
                }
            }
        }
        if (c0 != 0xFFFFu) atomicAdd(&bucket[c0], 1u);
        if (c1 != 0xFFFFu) atomicAdd(&bucket[c1], 1u);
        ch[t] = c0 | (c1 << 16);
    }
    __syncthreads();

    // ---- Phase C back half: exact pixel-order ranks (proven) ----
    if (t < CHUNK_PIX) {
        unsigned int r0 = 0, r1 = 0;
        if (c0 != 0xFFFFu) {
            for (int q = 0; q < t; q++) {
                unsigned int wv = ch[q];
                unsigned int lo = wv & 0xFFFFu, hi = wv >> 16;
                r0 += (lo == c0) + (hi == c0);
                r1 += (lo == c1) + (hi == c1);
            }
        }
        int p = b * HWn + hw;
        g_rec[2*p + 0] = (c0 != 0xFFFFu) ? ((c0 << 16) | r0) : 0xFFFFFFFFu;
        g_rec[2*p + 1] = (c1 != 0xFFFFu) ? ((c1 << 16) | r1) : 0xFFFFFFFFu;
    }
    if (t < Cn)
        g_cnt[(b * Cn + t) * NCHUNK + chunk] = bucket[t];
}

// ---------------------------------------------------------------------------
// K3a: 400 blocks x 1024 counts + last-block k3b base scan (R13-proven).
__global__ void __launch_bounds__(K3A_TPB) k3a_scan() {
    int sb = blockIdx.x;
    int t = threadIdx.x;
    int lane = t & 31;
    int warp = t >> 5;
    unsigned int v = g_cnt[sb * K3A_TPB + t];
    unsigned int incl = v;
    #pragma unroll
    for (int off = 1; off < 32; off <<= 1) {
        unsigned int n = __shfl_up_sync(0xFFFFFFFFu, incl, off);
        if (lane >= off) incl += n;
    }
    __shared__ unsigned int ws[32];
    if (lane == 31) ws[warp] = incl;
    __syncthreads();
    if (t < 32) {
        unsigned int w = ws[t];
        unsigned int iw = w;
        #pragma unroll
        for (int off = 1; off < 32; off <<= 1) {
            unsigned int n = __shfl_up_sync(0xFFFFFFFFu, iw, off);
            if (t >= off) iw += n;
        }
        ws[t] = iw - w;                     // exclusive warp base
        if (t == 31) g_bsum[sb] = iw;       // superblock total
    }
    __syncthreads();
    g_off[sb * K3A_TPB + t] = ws[warp] + (incl - v);

    // ---- last-block merge of the k3b base scan ----
    __threadfence();
    __shared__ unsigned int s_last;
    if (t == 0) {
        unsigned int old = atomicAdd(&g_done, 1u);
        s_last = (old == K3A_BLKS - 1) ? 1u : 0u;
    }
    __syncthreads();
    if (s_last) {
        unsigned int bv = (t < K3A_BLKS) ? g_bsum[t] : 0u;
        unsigned int bincl = bv;
        #pragma unroll
        for (int off = 1; off < 32; off <<= 1) {
            unsigned int n = __shfl_up_sync(0xFFFFFFFFu, bincl, off);
            if (lane >= off) bincl += n;
        }
        __shared__ unsigned int ws2[32];
        if (lane == 31) ws2[warp] = bincl;
        __syncthreads();
        if (t < 32) {
            unsigned int wv = ws2[t];
            unsigned int iw = wv;
            #pragma unroll
            for (int off = 1; off < 32; off <<= 1) {
                unsigned int n = __shfl_up_sync(0xFFFFFFFFu, iw, off);
                if (t >= off) iw += n;
            }
            ws2[t] = iw - wv;
        }
        __syncthreads();
        if (t < K3A_BLKS) g_bbase[t] = ws2[warp] + (bincl - bv);
    }
}

// ---------------------------------------------------------------------------
// K4: place each detection at its globally sorted position (proven).
__global__ void __launch_bounds__(CHUNK_PIX) k4_write(float* __restrict__ out, int nmax) {
    int blk = blockIdx.x;
    int t = threadIdx.x;
    int b     = blk / NCHUNK;
    int chunk = blk - b * NCHUNK;
    int hw = chunk * CHUNK_PIX + t;
    int p  = b * HWn + hw;
    float h = (float)(hw / Wn);
    float w = (float)(hw % Wn);
    float* kp = out + 2u * (unsigned)nmax;
    #pragma unroll
    for (int slot = 0; slot < 2; slot++) {
        unsigned int rec = g_rec[2*p + slot];
        if (rec != 0xFFFFFFFFu) {
            unsigned int c    = rec >> 16;
            unsigned int rank = rec & 0xFFFFu;
            unsigned int idx  = (unsigned)((b * Cn + (int)c) * NCHUNK + chunk);
            unsigned int n = g_bbase[idx >> 10] + g_off[idx] + rank;
            if (n < (unsigned)nmax) {
                out[2u*n + 0u] = h;
                out[2u*n + 1u] = w;
                kp [2u*n + 0u] = 8.0f * h + 3.5f;   // ((p*2+.5)*2+.5)*2+.5
                kp [2u*n + 1u] = 8.0f * w + 3.5f;
            }
        }
    }
}

// ---------------------------------------------------------------------------
extern "C" void kernel_launch(void* const* d_in, const int* in_sizes, int n_in,
                              void* d_out, int out_size) {
    const float* x = (const float*)d_in[0];
    float* out = (float*)d_out;
    int nmax = out_size / 4;
    int n4 = out_size / 4;          // float4 count
    int half4 = (out_size / 2) / 4;

    kfused<<<NBLK, TPB_F>>>(x, (float4*)out, n4, half4);  // bitmask ties + parallel 3x3
    k3a_scan<<<K3A_BLKS, K3A_TPB>>>();                    // scan + last-block bases
    k4_write<<<NBLK, CHUNK_PIX>>>(out, nmax);
}